// round 13
// baseline (speedup 1.0000x reference)
#include <cuda_runtime.h>
#include <math.h>
#include <stdint.h>

#define NR   65536
#define DIM  256
#define NCW  1024
#define NLEV 4
#define NPAIRS (NCW*(NCW-1)/2)
#define PD_BLOCKS 36

// GEMM geometry: CTA 128 rows x 256 cols per pass, 4 passes, K' = 1024 (4-term TF32)
#define GM 128
#define GN 256
#define NPASS 4
#define NCHUNK 32
#define TOTCHUNK (NPASS*NCHUNK)
#define SMEM_STRIDE 36
#define A_FLOATS (128*SMEM_STRIDE)
#define B_FLOATS (256*SMEM_STRIDE)
#define STAGE_FLOATS (A_FLOATS + B_FLOATS)
#define DYN_SMEM (2*STAGE_FLOATS*4)

#define KMAX 0xFFFFFFFFFFFFFFFFULL

// -------- device scratch --------
__device__ float g_resid[(size_t)NR*DIM];
__device__ float g_A[(size_t)NR*512];            // [ahi(256) | alo(256)]
__device__ float g_B[(size_t)NCW*1024];          // [bhi | bhi | blo | blo]
__device__ float g_rn2[NR];
__device__ float g_wk2[NCW];
__device__ int4  g_top4[NR];
__device__ int   g_idx[NR];
__device__ int   g_counts[NCW];
__device__ double g_qpart[NR];
__device__ double g_pdpart[PD_BLOCKS];
__device__ double g_scal[3];

// -------- helpers --------
__device__ __forceinline__ uint32_t smem_u32(const void* p) {
    uint32_t a;
    asm("{ .reg .u64 t; cvta.to.shared.u64 t, %1; cvt.u32.u64 %0, t; }" : "=r"(a) : "l"(p));
    return a;
}
__device__ __forceinline__ float tf32_round(float v) {
    float r;
    asm("cvt.rna.tf32.f32 %0, %1;" : "=f"(r) : "f"(v));
    return r;
}
__device__ __forceinline__ void cp16(uint32_t sdst, const float* gsrc) {
    asm volatile("cp.async.cg.shared.global [%0], [%1], 16;" :: "r"(sdst), "l"(gsrc));
}
__device__ __forceinline__ void cp_commit() {
    asm volatile("cp.async.commit_group;" ::: "memory");
}
__device__ __forceinline__ void cp_wait1() {
    asm volatile("cp.async.wait_group 1;" ::: "memory");
}
__device__ __forceinline__ void cp_wait0() {
    asm volatile("cp.async.wait_group 0;" ::: "memory");
}
__device__ __forceinline__ void mma_tf32(float* c, const uint32_t* a,
                                         uint32_t b0, uint32_t b1) {
    asm volatile(
        "mma.sync.aligned.m16n8k8.row.col.f32.tf32.tf32.f32 "
        "{%0,%1,%2,%3}, {%4,%5,%6,%7}, {%8,%9}, {%0,%1,%2,%3};"
        : "+f"(c[0]), "+f"(c[1]), "+f"(c[2]), "+f"(c[3])
        : "r"(a[0]), "r"(a[1]), "r"(a[2]), "r"(a[3]), "r"(b0), "r"(b1));
}
__device__ __forceinline__ unsigned long long dist_key(float dist, int col) {
    unsigned u = __float_as_uint(dist);
    u = (u & 0x80000000u) ? ~u : (u | 0x80000000u);
    return ((unsigned long long)u << 32) | (unsigned)col;
}
__device__ __forceinline__ void cswap(unsigned long long& a, unsigned long long& b) {
    unsigned long long lo = min(a, b), hi = max(a, b);
    a = lo; b = hi;
}
// merge two sorted ascending quads, keep lowest 4 (sorted)
__device__ __forceinline__ void merge4(unsigned long long* k,
                                       unsigned long long o0, unsigned long long o1,
                                       unsigned long long o2, unsigned long long o3) {
    unsigned long long c0 = min(k[0], o3);
    unsigned long long c1 = min(k[1], o2);
    unsigned long long c2 = min(k[2], o1);
    unsigned long long c3 = min(k[3], o0);
    cswap(c0, c2); cswap(c1, c3); cswap(c0, c1); cswap(c2, c3);
    k[0] = c0; k[1] = c1; k[2] = c2; k[3] = c3;
}
// sorted insert into ascending quad
__device__ __forceinline__ void upd4(float dot, float rn, float wk, int col,
                                     unsigned long long* k) {
    float dist = __fsub_rn(__fadd_rn(rn, wk), __fmul_rn(2.f, dot));
    unsigned long long key = dist_key(dist, col);
    if (key < k[3]) {
        k[3] = key;
        cswap(k[2], k[3]); cswap(k[1], k[2]); cswap(k[0], k[1]);
    }
}

// -------- zero scalar accumulators --------
__global__ void zero_kernel() {
    if (threadIdx.x < 3) g_scal[threadIdx.x] = 0.0;
}

// -------- B split + wk2 + counts reset --------
__global__ void bsplit_kernel(const float* __restrict__ W) {
    int c = blockIdx.x, t = threadIdx.x;
    float w = W[(size_t)c*DIM + t];
    float hi = tf32_round(w);
    float lo = tf32_round(__fsub_rn(w, hi));
    g_B[(size_t)c*1024 + t]        = hi;
    g_B[(size_t)c*1024 + 256 + t]  = hi;
    g_B[(size_t)c*1024 + 512 + t]  = lo;
    g_B[(size_t)c*1024 + 768 + t]  = lo;
    __shared__ float s[DIM];
    s[t] = __fmul_rn(w, w);
    __syncthreads();
    for (int off = 128; off > 0; off >>= 1) {
        if (t < off) s[t] = __fadd_rn(s[t], s[t+off]);
        __syncthreads();
    }
    if (t == 0) { g_wk2[c] = s[0]; g_counts[c] = 0; }
}

// -------- A split + rn2 --------
__global__ void asplit_kernel(const float* __restrict__ x, int first) {
    int n = blockIdx.x, t = threadIdx.x;
    const float* src = first ? x : g_resid;
    float v = src[(size_t)n*DIM + t];
    float hi = tf32_round(v);
    float lo = tf32_round(__fsub_rn(v, hi));
    g_A[(size_t)n*512 + t]       = hi;
    g_A[(size_t)n*512 + 256 + t] = lo;
    __shared__ float s[DIM];
    s[t] = __fmul_rn(v, v);
    __syncthreads();
    for (int off = 128; off > 0; off >>= 1) {
        if (t < off) s[t] = __fadd_rn(s[t], s[t+off]);
        __syncthreads();
    }
    if (t == 0) g_rn2[n] = s[0];
}

// -------- pairwise distances (compact loss): tiled Gram kernel --------
#define PDK 32
__global__ void __launch_bounds__(256)
pdist_kernel(const float* __restrict__ W) {
    int b = blockIdx.x, ti = 0;
    while (b >= 8 - ti) { b -= 8 - ti; ti++; }
    int tj = ti + b;

    __shared__ float sA[PDK][128];
    __shared__ float sB[PDK][128];

    int t = threadIdx.x;
    int tx = t & 15, ty = t >> 4;
    int rowBase = ti * 128, colBase = tj * 128;

    float acc[8][8];
    #pragma unroll
    for (int i = 0; i < 8; i++)
        #pragma unroll
        for (int j = 0; j < 8; j++) acc[i][j] = 0.f;

    int lrow = t >> 1;
    int lc0  = (t & 1) * 16;

    for (int kc = 0; kc < DIM; kc += PDK) {
        #pragma unroll
        for (int q = 0; q < 4; q++) {
            float4 va = *(const float4*)&W[(size_t)(rowBase + lrow)*DIM + kc + lc0 + q*4];
            float4 vb = *(const float4*)&W[(size_t)(colBase + lrow)*DIM + kc + lc0 + q*4];
            sA[lc0 + q*4 + 0][lrow] = va.x; sA[lc0 + q*4 + 1][lrow] = va.y;
            sA[lc0 + q*4 + 2][lrow] = va.z; sA[lc0 + q*4 + 3][lrow] = va.w;
            sB[lc0 + q*4 + 0][lrow] = vb.x; sB[lc0 + q*4 + 1][lrow] = vb.y;
            sB[lc0 + q*4 + 2][lrow] = vb.z; sB[lc0 + q*4 + 3][lrow] = vb.w;
        }
        __syncthreads();
        #pragma unroll 8
        for (int k = 0; k < PDK; k++) {
            float4 a0 = *(const float4*)&sA[k][ty*8];
            float4 a1 = *(const float4*)&sA[k][ty*8 + 4];
            float4 b0 = *(const float4*)&sB[k][tx*8];
            float4 b1 = *(const float4*)&sB[k][tx*8 + 4];
            float a[8] = {a0.x,a0.y,a0.z,a0.w,a1.x,a1.y,a1.z,a1.w};
            float bb[8] = {b0.x,b0.y,b0.z,b0.w,b1.x,b1.y,b1.z,b1.w};
            #pragma unroll
            for (int i = 0; i < 8; i++)
                #pragma unroll
                for (int j = 0; j < 8; j++)
                    acc[i][j] = __fmaf_rn(a[i], bb[j], acc[i][j]);
        }
        __syncthreads();
    }

    double dsum = 0.0;
    #pragma unroll
    for (int i = 0; i < 8; i++) {
        int gi = rowBase + ty*8 + i;
        float sqi = g_wk2[gi];
        #pragma unroll
        for (int j = 0; j < 8; j++) {
            int gj = colBase + tx*8 + j;
            if (gj > gi) {
                float d2 = __fsub_rn(__fadd_rn(sqi, g_wk2[gj]),
                                     __fmul_rn(2.f, acc[i][j]));
                dsum += (double)sqrtf(fmaxf(d2, 0.f));
            }
        }
    }
    __shared__ double sd[256];
    sd[t] = dsum;
    __syncthreads();
    for (int off = 128; off > 0; off >>= 1) {
        if (t < off) sd[t] += sd[t+off];
        __syncthreads();
    }
    if (t == 0) g_pdpart[blockIdx.x] = sd[0];
}

// -------- chunk loader --------
__device__ __forceinline__ void load_chunk(int p, int rowBase, uint32_t smbase, int t) {
    int pass = p >> 5, c = p & 31, s = p & 1;
    uint32_t Ab = smbase + (uint32_t)(s * STAGE_FLOATS * 4);
    uint32_t Bb = Ab + A_FLOATS * 4;
    int acol = ((c >> 3) & 1) * 256 + (c & 7) * 32;   // segs: hi,lo,hi,lo
    const float* Ag = g_A + (size_t)rowBase * 512 + acol;
    const float* Bg = g_B + (size_t)(pass * GN) * 1024 + c * 32;
    #pragma unroll
    for (int i = 0; i < 4; i++) {
        int u = t + i*256, r = u >> 3, q = u & 7;
        cp16(Ab + (uint32_t)(r*SMEM_STRIDE + q*4)*4, Ag + (size_t)r*512 + q*4);
    }
    #pragma unroll
    for (int i = 0; i < 8; i++) {
        int u = t + i*256, r = u >> 3, q = u & 7;
        cp16(Bb + (uint32_t)(r*SMEM_STRIDE + q*4)*4, Bg + (size_t)r*1024 + q*4);
    }
    cp_commit();
}

// -------- main GEMM (4xTF32 mma.sync) + top-4 argmin --------
__global__ void __launch_bounds__(256, 1)
gemm_argmin_kernel() {
    extern __shared__ float dynsm[];
    __shared__ unsigned long long sk[128][2][4];

    int t = threadIdx.x;
    int wid = t >> 5, lane = t & 31;
    int g = lane >> 2, tq = lane & 3;
    int warpRow = (wid >> 1) * 32;
    int warpCol = (wid & 1) * 128;
    int rowBase = blockIdx.x * GM;

    uint32_t smbase = smem_u32(dynsm);
    load_chunk(0, rowBase, smbase, t);
    load_chunk(1, rowBase, smbase, t);

    int r0 = rowBase + warpRow + g;
    float rn[4] = { g_rn2[r0], g_rn2[r0+8], g_rn2[r0+16], g_rn2[r0+24] };

    unsigned long long k4[4][4];
    #pragma unroll
    for (int i = 0; i < 4; i++)
        #pragma unroll
        for (int r = 0; r < 4; r++) k4[i][r] = KMAX;

    for (int pass = 0; pass < NPASS; pass++) {
        float acc[2][16][4];
        #pragma unroll
        for (int mi = 0; mi < 2; mi++)
            #pragma unroll
            for (int ni = 0; ni < 16; ni++)
                #pragma unroll
                for (int q = 0; q < 4; q++) acc[mi][ni][q] = 0.f;

        for (int c = 0; c < NCHUNK; c++) {
            int p = pass * NCHUNK + c, s = p & 1;
            if (p + 2 >= TOTCHUNK) cp_wait0(); else cp_wait1();
            __syncthreads();

            const uint32_t* As = (const uint32_t*)(dynsm + s * STAGE_FLOATS);
            const uint32_t* Bs = As + A_FLOATS;

            #pragma unroll
            for (int ks = 0; ks < 4; ks++) {
                int k0 = ks * 8 + tq;
                uint32_t a[2][4];
                #pragma unroll
                for (int mi = 0; mi < 2; mi++) {
                    int rr = warpRow + mi*16 + g;
                    a[mi][0] = As[rr*SMEM_STRIDE + k0];
                    a[mi][1] = As[(rr+8)*SMEM_STRIDE + k0];
                    a[mi][2] = As[rr*SMEM_STRIDE + k0 + 4];
                    a[mi][3] = As[(rr+8)*SMEM_STRIDE + k0 + 4];
                }
                #pragma unroll
                for (int ni = 0; ni < 16; ni++) {
                    int cc = warpCol + ni*8 + g;
                    uint32_t b0 = Bs[cc*SMEM_STRIDE + k0];
                    uint32_t b1 = Bs[cc*SMEM_STRIDE + k0 + 4];
                    mma_tf32(acc[0][ni], a[0], b0, b1);
                    mma_tf32(acc[1][ni], a[1], b0, b1);
                }
            }
            __syncthreads();
            if (p + 2 < TOTCHUNK) load_chunk(p + 2, rowBase, smbase, t);
        }

        int n0 = pass * GN;
        #pragma unroll
        for (int ni = 0; ni < 16; ni++) {
            int col = n0 + warpCol + ni*8 + 2*tq;
            float wka = __ldg(&g_wk2[col]);
            float wkb = __ldg(&g_wk2[col + 1]);
            #pragma unroll
            for (int mi = 0; mi < 2; mi++) {
                upd4(acc[mi][ni][0], rn[mi*2],   wka, col,   k4[mi*2]);
                upd4(acc[mi][ni][1], rn[mi*2],   wkb, col+1, k4[mi*2]);
                upd4(acc[mi][ni][2], rn[mi*2+1], wka, col,   k4[mi*2+1]);
                upd4(acc[mi][ni][3], rn[mi*2+1], wkb, col+1, k4[mi*2+1]);
            }
        }
    }

    // quad reduce: lanes sharing a row are l = g*4 + tq
    #pragma unroll
    for (int i = 0; i < 4; i++) {
        #pragma unroll
        for (int off = 1; off <= 2; off <<= 1) {
            unsigned long long o0 = __shfl_xor_sync(0xFFFFFFFFu, k4[i][0], off);
            unsigned long long o1 = __shfl_xor_sync(0xFFFFFFFFu, k4[i][1], off);
            unsigned long long o2 = __shfl_xor_sync(0xFFFFFFFFu, k4[i][2], off);
            unsigned long long o3 = __shfl_xor_sync(0xFFFFFFFFu, k4[i][3], off);
            merge4(k4[i], o0, o1, o2, o3);
        }
    }
    if (tq == 0) {
        #pragma unroll
        for (int i = 0; i < 4; i++)
            #pragma unroll
            for (int r = 0; r < 4; r++)
                sk[warpRow + g + i*8][wid & 1][r] = k4[i][r];
    }
    __syncthreads();
    if (t < 128) {
        unsigned long long m[4] = { sk[t][0][0], sk[t][0][1], sk[t][0][2], sk[t][0][3] };
        merge4(m, sk[t][1][0], sk[t][1][1], sk[t][1][2], sk[t][1][3]);
        g_top4[rowBase + t] = make_int4((int)(m[0] & 0xFFFFFFFFULL),
                                        (int)(m[1] & 0xFFFFFFFFULL),
                                        (int)(m[2] & 0xFFFFFFFFULL),
                                        (int)(m[3] & 0xFFFFFFFFULL));
    }
}

// -------- exact refine: sequential-FMA dots (replicates the R3 kernel's
// -------- accumulation order, which matched the reference on all indices) --------
__global__ void __launch_bounds__(64)
refine_kernel(const float* __restrict__ x, const float* __restrict__ W, int first) {
    int n = blockIdx.x, t = threadIdx.x;
    __shared__ float rs[DIM];
    __shared__ unsigned long long keys[4];
    int4 cand = g_top4[n];
    const float* src = first ? x : g_resid;
    float4 v = *(const float4*)&src[(size_t)n*DIM + t*4];
    rs[t*4+0] = v.x; rs[t*4+1] = v.y; rs[t*4+2] = v.z; rs[t*4+3] = v.w;
    __syncthreads();
    if (t < 4) {
        int c = (t == 0) ? cand.x : (t == 1) ? cand.y : (t == 2) ? cand.z : cand.w;
        const float* w = W + (size_t)c * DIM;
        float acc = 0.f;
        #pragma unroll 16
        for (int k = 0; k < DIM; k++)
            acc = __fmaf_rn(rs[k], __ldg(&w[k]), acc);
        float d = __fsub_rn(__fadd_rn(g_rn2[n], g_wk2[c]), __fmul_rn(2.f, acc));
        keys[t] = dist_key(d, c);
    }
    __syncthreads();
    if (t == 0) {
        unsigned long long bk = min(min(keys[0], keys[1]), min(keys[2], keys[3]));
        g_idx[n] = (int)(bk & 0xFFFFFFFFULL);
    }
}

// -------- per-row update: gather, straight-through, residual, losses --------
__global__ void update_kernel(const float* __restrict__ x, const float* __restrict__ W,
                              float* __restrict__ quant, float* __restrict__ out_idx,
                              int first) {
    int n = blockIdx.x, t = threadIdx.x;
    int idx = g_idx[n];
    size_t e = (size_t)n * DIM + t;
    const float* srcr = first ? x : g_resid;
    float r = srcr[e];
    float q = W[(size_t)idx * DIM + t];
    float diff = __fsub_rn(q, r);
    float qst  = __fadd_rn(r, diff);
    float qz   = first ? qst : __fadd_rn(quant[e], qst);
    quant[e] = qz;
    float rnew = __fsub_rn(x[e], qz);
    g_resid[e] = rnew;

    __shared__ double sd[DIM];
    sd[t] = (double)diff * (double)diff;
    __syncthreads();
    for (int off = 128; off > 0; off >>= 1) {
        if (t < off) sd[t] += sd[t+off];
        __syncthreads();
    }
    if (t == 0) {
        g_qpart[n] = sd[0];
        out_idx[n] = (float)idx;
        atomicAdd(&g_counts[idx], 1);
    }
}

// -------- per-level scalar reductions (deterministic) --------
__global__ void level_reduce_kernel() {
    __shared__ double sd[1024];
    int t = threadIdx.x;
    double a = 0.0;
    for (int i = t; i < NR; i += 1024) a += g_qpart[i];
    sd[t] = a;
    __syncthreads();
    for (int off = 512; off > 0; off >>= 1) {
        if (t < off) sd[t] += sd[t+off];
        __syncthreads();
    }
    if (t == 0) {
        double m = sd[0] / ((double)NR * (double)DIM);
        g_scal[0] += m + 0.25 * m;
    }
    __syncthreads();
    sd[t] = fabs((double)g_counts[t] - 64.0);
    __syncthreads();
    for (int off = 512; off > 0; off >>= 1) {
        if (t < off) sd[t] += sd[t+off];
        __syncthreads();
    }
    if (t == 0) g_scal[1] += sd[0] / (double)NCW;
    __syncthreads();
    sd[t] = (t < PD_BLOCKS) ? g_pdpart[t] : 0.0;
    __syncthreads();
    for (int off = 512; off > 0; off >>= 1) {
        if (t < off) sd[t] += sd[t+off];
        __syncthreads();
    }
    if (t == 0) g_scal[2] += 2.0 * (sd[0] / (double)NPAIRS);
}

__global__ void finalize_kernel(float* __restrict__ scal_out) {
    if (threadIdx.x < 3) scal_out[threadIdx.x] = (float)g_scal[threadIdx.x];
}

// -------- host driver --------
extern "C" void kernel_launch(void* const* d_in, const int* in_sizes, int n_in,
                              void* d_out, int out_size) {
    const float* x  = (const float*)d_in[0];
    const float* cb = (const float*)d_in[1];
    float* out   = (float*)d_out;
    float* quant = out;
    float* scal  = out + (size_t)NR * DIM;
    float* oidx  = scal + 3;

    cudaFuncSetAttribute(gemm_argmin_kernel,
                         cudaFuncAttributeMaxDynamicSharedMemorySize, DYN_SMEM);

    zero_kernel<<<1, 32>>>();
    for (int c = 0; c < NLEV; c++) {
        const float* W = cb + (size_t)c * NCW * DIM;
        int first = (c == 0) ? 1 : 0;
        bsplit_kernel<<<NCW, 256>>>(W);
        asplit_kernel<<<NR, 256>>>(x, first);
        pdist_kernel<<<PD_BLOCKS, 256>>>(W);
        gemm_argmin_kernel<<<NR/GM, 256, DYN_SMEM>>>();
        refine_kernel<<<NR, 64>>>(x, W, first);
        update_kernel<<<NR, 256>>>(x, W, quant, oidx + (size_t)c * NR, first);
        level_reduce_kernel<<<1, 1024>>>();
    }
    finalize_kernel<<<1, 32>>>(scal);
}

// round 14
// speedup vs baseline: 1.6084x; 1.6084x over previous
#include <cuda_runtime.h>
#include <cuda_bf16.h>
#include <math.h>
#include <stdint.h>

#define NR   65536
#define DIM  256
#define NCW  1024
#define NLEV 4
#define NPAIRS (NCW*(NCW-1)/2)
#define PD_BLOCKS 36

// GEMM geometry: CTA 128 rows x 128 cols per pass, 8 passes, K' = 768 bf16 (3-term)
#define GM 128
#define GNP 128
#define NPASS 8
#define NCHUNK 24            // chunks per pass, 32 bf16 of K' each
#define TOTCHUNK (NPASS*NCHUNK)
#define ROW_U32 20           // 16 data u32 (32 bf16) + 4 pad -> conflict-free
#define A_BYTES (128*ROW_U32*4)      // 10240
#define B_BYTES (128*ROW_U32*4)      // 10240
#define STAGE_BYTES (A_BYTES+B_BYTES)
#define DYN_SMEM (2*STAGE_BYTES)     // 40960

#define KMAX 0xFFFFFFFFFFFFFFFFULL

// -------- device scratch --------
__device__ float    g_resid[(size_t)NR*DIM];
__device__ uint32_t g_Abf[(size_t)NR*256];    // per row: [hi(128 u32) | lo(128 u32)]
__device__ uint32_t g_Bbf[(size_t)NCW*384];   // per row: [hi | hi | lo]
__device__ float    g_rn2[NR];
__device__ float    g_wk2[NCW];
__device__ int2     g_top2[NR];
__device__ int      g_idx[NR];
__device__ int      g_counts[NCW];
__device__ double   g_qpart[NR];
__device__ double   g_pdpart[PD_BLOCKS];
__device__ double   g_scal[3];

// -------- helpers --------
__device__ __forceinline__ uint32_t smem_u32(const void* p) {
    uint32_t a;
    asm("{ .reg .u64 t; cvta.to.shared.u64 t, %1; cvt.u32.u64 %0, t; }" : "=r"(a) : "l"(p));
    return a;
}
__device__ __forceinline__ void cp16(uint32_t sdst, const void* gsrc) {
    asm volatile("cp.async.cg.shared.global [%0], [%1], 16;" :: "r"(sdst), "l"(gsrc));
}
__device__ __forceinline__ void cp_commit() {
    asm volatile("cp.async.commit_group;" ::: "memory");
}
__device__ __forceinline__ void cp_wait1() {
    asm volatile("cp.async.wait_group 1;" ::: "memory");
}
__device__ __forceinline__ void cp_wait0() {
    asm volatile("cp.async.wait_group 0;" ::: "memory");
}
__device__ __forceinline__ void mma_bf16(float* c, const uint32_t* a,
                                         uint32_t b0, uint32_t b1) {
    asm volatile(
        "mma.sync.aligned.m16n8k16.row.col.f32.bf16.bf16.f32 "
        "{%0,%1,%2,%3}, {%4,%5,%6,%7}, {%8,%9}, {%0,%1,%2,%3};"
        : "+f"(c[0]), "+f"(c[1]), "+f"(c[2]), "+f"(c[3])
        : "r"(a[0]), "r"(a[1]), "r"(a[2]), "r"(a[3]), "r"(b0), "r"(b1));
}
__device__ __forceinline__ unsigned long long dist_key(float dist, int col) {
    unsigned u = __float_as_uint(dist);
    u = (u & 0x80000000u) ? ~u : (u | 0x80000000u);
    return ((unsigned long long)u << 32) | (unsigned)col;
}
__device__ __forceinline__ void upd2(float dot, float rn, float wk, int col,
                                     unsigned long long& b, unsigned long long& s) {
    float dist = __fsub_rn(__fadd_rn(rn, wk), __fmul_rn(2.f, dot));
    unsigned long long key = dist_key(dist, col);
    if (key < b) { s = b; b = key; }
    else if (key < s) { s = key; }
}
__device__ __forceinline__ void merge2(unsigned long long& b, unsigned long long& s,
                                       unsigned long long ob, unsigned long long os) {
    unsigned long long nb = min(b, ob);
    unsigned long long ns = min(max(b, ob), min(s, os));
    b = nb; s = ns;
}

// -------- zero scalar accumulators --------
__global__ void zero_kernel() {
    if (threadIdx.x < 3) g_scal[threadIdx.x] = 0.0;
}

// -------- B split (bf16 hi/lo) + wk2 + counts reset --------
__global__ void bsplit_kernel(const float* __restrict__ W) {
    int c = blockIdx.x, t = threadIdx.x;
    float w = W[(size_t)c*DIM + t];
    __nv_bfloat16 hb = __float2bfloat16(w);
    float hf = __bfloat162float(hb);
    __nv_bfloat16 lb = __float2bfloat16(__fsub_rn(w, hf));
    unsigned short hu = __bfloat16_as_ushort(hb);
    unsigned short lu = __bfloat16_as_ushort(lb);
    unsigned short hn = __shfl_down_sync(0xFFFFFFFFu, hu, 1);
    unsigned short ln = __shfl_down_sync(0xFFFFFFFFu, lu, 1);
    if ((t & 1) == 0) {
        uint32_t hp = (uint32_t)hu | ((uint32_t)hn << 16);
        uint32_t lp = (uint32_t)lu | ((uint32_t)ln << 16);
        int k2 = t >> 1;
        g_Bbf[(size_t)c*384 + k2]       = hp;
        g_Bbf[(size_t)c*384 + 128 + k2] = hp;
        g_Bbf[(size_t)c*384 + 256 + k2] = lp;
    }
    __shared__ float s[DIM];
    s[t] = __fmul_rn(w, w);
    __syncthreads();
    for (int off = 128; off > 0; off >>= 1) {
        if (t < off) s[t] = __fadd_rn(s[t], s[t+off]);
        __syncthreads();
    }
    if (t == 0) { g_wk2[c] = s[0]; g_counts[c] = 0; }
}

// -------- A split (bf16 hi/lo) + rn2 --------
__global__ void asplit_kernel(const float* __restrict__ x, int first) {
    int n = blockIdx.x, t = threadIdx.x;
    const float* src = first ? x : g_resid;
    float v = src[(size_t)n*DIM + t];
    __nv_bfloat16 hb = __float2bfloat16(v);
    float hf = __bfloat162float(hb);
    __nv_bfloat16 lb = __float2bfloat16(__fsub_rn(v, hf));
    unsigned short hu = __bfloat16_as_ushort(hb);
    unsigned short lu = __bfloat16_as_ushort(lb);
    unsigned short hn = __shfl_down_sync(0xFFFFFFFFu, hu, 1);
    unsigned short ln = __shfl_down_sync(0xFFFFFFFFu, lu, 1);
    if ((t & 1) == 0) {
        uint32_t hp = (uint32_t)hu | ((uint32_t)hn << 16);
        uint32_t lp = (uint32_t)lu | ((uint32_t)ln << 16);
        int k2 = t >> 1;
        g_Abf[(size_t)n*256 + k2]       = hp;
        g_Abf[(size_t)n*256 + 128 + k2] = lp;
    }
    __shared__ float s[DIM];
    s[t] = __fmul_rn(v, v);
    __syncthreads();
    for (int off = 128; off > 0; off >>= 1) {
        if (t < off) s[t] = __fadd_rn(s[t], s[t+off]);
        __syncthreads();
    }
    if (t == 0) g_rn2[n] = s[0];
}

// -------- pairwise distances (compact loss): tiled Gram kernel --------
#define PDK 32
__global__ void __launch_bounds__(256)
pdist_kernel(const float* __restrict__ W) {
    int b = blockIdx.x, ti = 0;
    while (b >= 8 - ti) { b -= 8 - ti; ti++; }
    int tj = ti + b;

    __shared__ float sA[PDK][128];
    __shared__ float sB[PDK][128];

    int t = threadIdx.x;
    int tx = t & 15, ty = t >> 4;
    int rowBase = ti * 128, colBase = tj * 128;

    float acc[8][8];
    #pragma unroll
    for (int i = 0; i < 8; i++)
        #pragma unroll
        for (int j = 0; j < 8; j++) acc[i][j] = 0.f;

    int lrow = t >> 1;
    int lc0  = (t & 1) * 16;

    for (int kc = 0; kc < DIM; kc += PDK) {
        #pragma unroll
        for (int q = 0; q < 4; q++) {
            float4 va = *(const float4*)&W[(size_t)(rowBase + lrow)*DIM + kc + lc0 + q*4];
            float4 vb = *(const float4*)&W[(size_t)(colBase + lrow)*DIM + kc + lc0 + q*4];
            sA[lc0 + q*4 + 0][lrow] = va.x; sA[lc0 + q*4 + 1][lrow] = va.y;
            sA[lc0 + q*4 + 2][lrow] = va.z; sA[lc0 + q*4 + 3][lrow] = va.w;
            sB[lc0 + q*4 + 0][lrow] = vb.x; sB[lc0 + q*4 + 1][lrow] = vb.y;
            sB[lc0 + q*4 + 2][lrow] = vb.z; sB[lc0 + q*4 + 3][lrow] = vb.w;
        }
        __syncthreads();
        #pragma unroll 8
        for (int k = 0; k < PDK; k++) {
            float4 a0 = *(const float4*)&sA[k][ty*8];
            float4 a1 = *(const float4*)&sA[k][ty*8 + 4];
            float4 b0 = *(const float4*)&sB[k][tx*8];
            float4 b1 = *(const float4*)&sB[k][tx*8 + 4];
            float a[8] = {a0.x,a0.y,a0.z,a0.w,a1.x,a1.y,a1.z,a1.w};
            float bb[8] = {b0.x,b0.y,b0.z,b0.w,b1.x,b1.y,b1.z,b1.w};
            #pragma unroll
            for (int i = 0; i < 8; i++)
                #pragma unroll
                for (int j = 0; j < 8; j++)
                    acc[i][j] = __fmaf_rn(a[i], bb[j], acc[i][j]);
        }
        __syncthreads();
    }

    double dsum = 0.0;
    #pragma unroll
    for (int i = 0; i < 8; i++) {
        int gi = rowBase + ty*8 + i;
        float sqi = g_wk2[gi];
        #pragma unroll
        for (int j = 0; j < 8; j++) {
            int gj = colBase + tx*8 + j;
            if (gj > gi) {
                float d2 = __fsub_rn(__fadd_rn(sqi, g_wk2[gj]),
                                     __fmul_rn(2.f, acc[i][j]));
                dsum += (double)sqrtf(fmaxf(d2, 0.f));
            }
        }
    }
    __shared__ double sd[256];
    sd[t] = dsum;
    __syncthreads();
    for (int off = 128; off > 0; off >>= 1) {
        if (t < off) sd[t] += sd[t+off];
        __syncthreads();
    }
    if (t == 0) g_pdpart[blockIdx.x] = sd[0];
}

// -------- chunk loader: A [128 x 16u32], B [128 x 16u32], padded stride 20 --------
__device__ __forceinline__ void load_chunk(int p, int rowBase, uint32_t smbase, int t) {
    int pass = p / NCHUNK, c = p % NCHUNK, s = p & 1;
    uint32_t Ab = smbase + (uint32_t)(s * STAGE_BYTES);
    uint32_t Bb = Ab + A_BYTES;
    int aoff = (c < 8) ? c*16 : (c < 16) ? 128 + (c-8)*16 : (c-16)*16;  // hi,lo,hi
    int boff = c * 16;                                                    // hi,hi,lo
    int n0 = pass * GNP;
    #pragma unroll
    for (int i = 0; i < 2; i++) {
        int f = t + i*256;          // 0..511
        int row = f >> 2, seg = f & 3;
        cp16(Ab + (uint32_t)(row*(ROW_U32*4) + seg*16),
             g_Abf + (size_t)(rowBase + row)*256 + aoff + seg*4);
        cp16(Bb + (uint32_t)(row*(ROW_U32*4) + seg*16),
             g_Bbf + (size_t)(n0 + row)*384 + boff + seg*4);
    }
    cp_commit();
}

// -------- main GEMM (3-term bf16 mma.sync m16n8k16) + top-2 argmin --------
__global__ void __launch_bounds__(256)
gemm_argmin_kernel() {
    extern __shared__ float dynsm[];
    __shared__ unsigned long long sbk[128][2], ssk[128][2];

    int t = threadIdx.x;
    int wid = t >> 5, lane = t & 31;
    int g = lane >> 2, tq = lane & 3;
    int warpRow = (wid >> 1) * 32;     // 4 row-groups of 32
    int warpCol = (wid & 1) * 64;      // 2 col-groups of 64
    int rowBase = blockIdx.x * GM;

    uint32_t smbase = smem_u32(dynsm);
    load_chunk(0, rowBase, smbase, t);
    load_chunk(1, rowBase, smbase, t);

    int r0 = rowBase + warpRow + g;
    float rn[4] = { g_rn2[r0], g_rn2[r0+8], g_rn2[r0+16], g_rn2[r0+24] };

    unsigned long long best[4], sec[4];
    #pragma unroll
    for (int i = 0; i < 4; i++) { best[i] = KMAX; sec[i] = KMAX; }

    for (int pass = 0; pass < NPASS; pass++) {
        float acc[2][8][4];
        #pragma unroll
        for (int mi = 0; mi < 2; mi++)
            #pragma unroll
            for (int ni = 0; ni < 8; ni++)
                #pragma unroll
                for (int q = 0; q < 4; q++) acc[mi][ni][q] = 0.f;

        for (int c = 0; c < NCHUNK; c++) {
            int p = pass * NCHUNK + c, s = p & 1;
            if (p + 2 >= TOTCHUNK) cp_wait0(); else cp_wait1();
            __syncthreads();

            const uint32_t* As = (const uint32_t*)dynsm + (size_t)s * (STAGE_BYTES/4);
            const uint32_t* Bs = As + A_BYTES/4;

            #pragma unroll
            for (int ks = 0; ks < 2; ks++) {
                int k0 = ks * 8 + tq;
                uint32_t a[2][4];
                #pragma unroll
                for (int mi = 0; mi < 2; mi++) {
                    int rr = warpRow + mi*16 + g;
                    a[mi][0] = As[rr*ROW_U32 + k0];
                    a[mi][1] = As[(rr+8)*ROW_U32 + k0];
                    a[mi][2] = As[rr*ROW_U32 + k0 + 4];
                    a[mi][3] = As[(rr+8)*ROW_U32 + k0 + 4];
                }
                #pragma unroll
                for (int ni = 0; ni < 8; ni++) {
                    int cc = warpCol + ni*8 + g;
                    uint32_t b0 = Bs[cc*ROW_U32 + k0];
                    uint32_t b1 = Bs[cc*ROW_U32 + k0 + 4];
                    mma_bf16(acc[0][ni], a[0], b0, b1);
                    mma_bf16(acc[1][ni], a[1], b0, b1);
                }
            }
            __syncthreads();
            if (p + 2 < TOTCHUNK) load_chunk(p + 2, rowBase, smbase, t);
        }

        int n0 = pass * GNP;
        #pragma unroll
        for (int ni = 0; ni < 8; ni++) {
            int col = n0 + warpCol + ni*8 + 2*tq;
            float wka = __ldg(&g_wk2[col]);
            float wkb = __ldg(&g_wk2[col + 1]);
            #pragma unroll
            for (int mi = 0; mi < 2; mi++) {
                upd2(acc[mi][ni][0], rn[mi*2],   wka, col,   best[mi*2],   sec[mi*2]);
                upd2(acc[mi][ni][1], rn[mi*2],   wkb, col+1, best[mi*2],   sec[mi*2]);
                upd2(acc[mi][ni][2], rn[mi*2+1], wka, col,   best[mi*2+1], sec[mi*2+1]);
                upd2(acc[mi][ni][3], rn[mi*2+1], wkb, col+1, best[mi*2+1], sec[mi*2+1]);
            }
        }
    }

    // quad reduce: lanes sharing a row are l = g*4 + tq
    #pragma unroll
    for (int i = 0; i < 4; i++) {
        #pragma unroll
        for (int off = 1; off <= 2; off <<= 1) {
            unsigned long long ob = __shfl_xor_sync(0xFFFFFFFFu, best[i], off);
            unsigned long long os = __shfl_xor_sync(0xFFFFFFFFu, sec[i],  off);
            merge2(best[i], sec[i], ob, os);
        }
    }
    if (tq == 0) {
        #pragma unroll
        for (int i = 0; i < 4; i++) {
            sbk[warpRow + g + i*8][wid & 1] = best[i];
            ssk[warpRow + g + i*8][wid & 1] = sec[i];
        }
    }
    __syncthreads();
    if (t < 128) {
        unsigned long long b = sbk[t][0], s = ssk[t][0];
        merge2(b, s, sbk[t][1], ssk[t][1]);
        g_top2[rowBase + t] = make_int2((int)(b & 0xFFFFFFFFULL),
                                        (int)(s & 0xFFFFFFFFULL));
    }
}

// -------- exact refine: sequential-FMA dots (R3-validated accumulation order) --------
__global__ void __launch_bounds__(64)
refine_kernel(const float* __restrict__ x, const float* __restrict__ W, int first) {
    int n = blockIdx.x, t = threadIdx.x;
    __shared__ float rs[DIM];
    __shared__ unsigned long long keys[2];
    int2 cand = g_top2[n];
    const float* src = first ? x : g_resid;
    float4 v = *(const float4*)&src[(size_t)n*DIM + t*4];
    rs[t*4+0] = v.x; rs[t*4+1] = v.y; rs[t*4+2] = v.z; rs[t*4+3] = v.w;
    __syncthreads();
    if (t < 2) {
        int c = (t == 0) ? cand.x : cand.y;
        const float* w = W + (size_t)c * DIM;
        float acc = 0.f;
        #pragma unroll 16
        for (int k = 0; k < DIM; k++)
            acc = __fmaf_rn(rs[k], __ldg(&w[k]), acc);
        float d = __fsub_rn(__fadd_rn(g_rn2[n], g_wk2[c]), __fmul_rn(2.f, acc));
        keys[t] = dist_key(d, c);
    }
    __syncthreads();
    if (t == 0) {
        unsigned long long bk = min(keys[0], keys[1]);
        g_idx[n] = (int)(bk & 0xFFFFFFFFULL);
    }
}

// -------- per-row update: gather, straight-through, residual, losses --------
__global__ void update_kernel(const float* __restrict__ x, const float* __restrict__ W,
                              float* __restrict__ quant, float* __restrict__ out_idx,
                              int first) {
    int n = blockIdx.x, t = threadIdx.x;
    int idx = g_idx[n];
    size_t e = (size_t)n * DIM + t;
    const float* srcr = first ? x : g_resid;
    float r = srcr[e];
    float q = W[(size_t)idx * DIM + t];
    float diff = __fsub_rn(q, r);
    float qst  = __fadd_rn(r, diff);
    float qz   = first ? qst : __fadd_rn(quant[e], qst);
    quant[e] = qz;
    float rnew = __fsub_rn(x[e], qz);
    g_resid[e] = rnew;

    __shared__ double sd[DIM];
    sd[t] = (double)diff * (double)diff;
    __syncthreads();
    for (int off = 128; off > 0; off >>= 1) {
        if (t < off) sd[t] += sd[t+off];
        __syncthreads();
    }
    if (t == 0) {
        g_qpart[n] = sd[0];
        out_idx[n] = (float)idx;
        atomicAdd(&g_counts[idx], 1);
    }
}

// -------- per-level scalar reductions (deterministic) --------
__global__ void level_reduce_kernel() {
    __shared__ double sd[1024];
    int t = threadIdx.x;
    double a = 0.0;
    for (int i = t; i < NR; i += 1024) a += g_qpart[i];
    sd[t] = a;
    __syncthreads();
    for (int off = 512; off > 0; off >>= 1) {
        if (t < off) sd[t] += sd[t+off];
        __syncthreads();
    }
    if (t == 0) {
        double m = sd[0] / ((double)NR * (double)DIM);
        g_scal[0] += m + 0.25 * m;
    }
    __syncthreads();
    sd[t] = fabs((double)g_counts[t] - 64.0);
    __syncthreads();
    for (int off = 512; off > 0; off >>= 1) {
        if (t < off) sd[t] += sd[t+off];
        __syncthreads();
    }
    if (t == 0) g_scal[1] += sd[0] / (double)NCW;
    __syncthreads();
    sd[t] = (t < PD_BLOCKS) ? g_pdpart[t] : 0.0;
    __syncthreads();
    for (int off = 512; off > 0; off >>= 1) {
        if (t < off) sd[t] += sd[t+off];
        __syncthreads();
    }
    if (t == 0) g_scal[2] += 2.0 * (sd[0] / (double)NPAIRS);
}

__global__ void finalize_kernel(float* __restrict__ scal_out) {
    if (threadIdx.x < 3) scal_out[threadIdx.x] = (float)g_scal[threadIdx.x];
}

// -------- host driver --------
extern "C" void kernel_launch(void* const* d_in, const int* in_sizes, int n_in,
                              void* d_out, int out_size) {
    const float* x  = (const float*)d_in[0];
    const float* cb = (const float*)d_in[1];
    float* out   = (float*)d_out;
    float* quant = out;
    float* scal  = out + (size_t)NR * DIM;
    float* oidx  = scal + 3;

    cudaFuncSetAttribute(gemm_argmin_kernel,
                         cudaFuncAttributeMaxDynamicSharedMemorySize, DYN_SMEM);

    zero_kernel<<<1, 32>>>();
    for (int c = 0; c < NLEV; c++) {
        const float* W = cb + (size_t)c * NCW * DIM;
        int first = (c == 0) ? 1 : 0;
        bsplit_kernel<<<NCW, 256>>>(W);
        asplit_kernel<<<NR, 256>>>(x, first);
        pdist_kernel<<<PD_BLOCKS, 256>>>(W);
        gemm_argmin_kernel<<<NR/GM, 256, DYN_SMEM>>>();
        refine_kernel<<<NR, 64>>>(x, W, first);
        update_kernel<<<NR, 256>>>(x, W, quant, oidx + (size_t)c * NR, first);
        level_reduce_kernel<<<1, 1024>>>();
    }
    finalize_kernel<<<1, 32>>>(scal);
}

// round 15
// speedup vs baseline: 1.8744x; 1.1654x over previous
#include <cuda_runtime.h>
#include <cuda_bf16.h>
#include <math.h>
#include <stdint.h>

#define NR   65536
#define DIM  256
#define NCW  1024
#define NLEV 4
#define NPAIRS (NCW*(NCW-1)/2)
#define PD_BLOCKS 36

// GEMM geometry: CTA 128 rows x 128 cols per pass, 8 passes, K = 256 bf16 (1-term hh)
#define GM 128
#define GNP 128
#define NPASS 8
#define NCHUNK 8             // chunks per pass, 32 bf16 of K each
#define TOTCHUNK (NPASS*NCHUNK)
#define ROW_U32 20           // 16 data u32 (32 bf16) + 4 pad -> conflict-free
#define A_BYTES (128*ROW_U32*4)      // 10240
#define B_BYTES (128*ROW_U32*4)      // 10240
#define STAGE_BYTES (A_BYTES+B_BYTES)
#define DYN_SMEM (2*STAGE_BYTES)     // 40960

#define KMAX 0xFFFFFFFFFFFFFFFFULL

// -------- device scratch --------
__device__ float    g_resid[(size_t)NR*DIM];
__device__ uint32_t g_Abf[(size_t)NR*128];    // per row: hi bf16 pairs (128 u32)
__device__ uint32_t g_Bbf[(size_t)NCW*128];   // per codeword: hi bf16 pairs
__device__ float    g_rn2[NR];
__device__ float    g_wk2[NCW];
__device__ int4     g_top4[NR];
__device__ int      g_idx[NR];
__device__ int      g_counts[NCW];
__device__ double   g_qpart[NR];
__device__ double   g_pdpart[PD_BLOCKS];
__device__ double   g_scal[3];

// -------- helpers --------
__device__ __forceinline__ uint32_t smem_u32(const void* p) {
    uint32_t a;
    asm("{ .reg .u64 t; cvta.to.shared.u64 t, %1; cvt.u32.u64 %0, t; }" : "=r"(a) : "l"(p));
    return a;
}
__device__ __forceinline__ void cp16(uint32_t sdst, const void* gsrc) {
    asm volatile("cp.async.cg.shared.global [%0], [%1], 16;" :: "r"(sdst), "l"(gsrc));
}
__device__ __forceinline__ void cp_commit() {
    asm volatile("cp.async.commit_group;" ::: "memory");
}
__device__ __forceinline__ void cp_wait1() {
    asm volatile("cp.async.wait_group 1;" ::: "memory");
}
__device__ __forceinline__ void cp_wait0() {
    asm volatile("cp.async.wait_group 0;" ::: "memory");
}
__device__ __forceinline__ void mma_bf16(float* c, const uint32_t* a,
                                         uint32_t b0, uint32_t b1) {
    asm volatile(
        "mma.sync.aligned.m16n8k16.row.col.f32.bf16.bf16.f32 "
        "{%0,%1,%2,%3}, {%4,%5,%6,%7}, {%8,%9}, {%0,%1,%2,%3};"
        : "+f"(c[0]), "+f"(c[1]), "+f"(c[2]), "+f"(c[3])
        : "r"(a[0]), "r"(a[1]), "r"(a[2]), "r"(a[3]), "r"(b0), "r"(b1));
}
__device__ __forceinline__ unsigned long long dist_key(float dist, int col) {
    unsigned u = __float_as_uint(dist);
    u = (u & 0x80000000u) ? ~u : (u | 0x80000000u);
    return ((unsigned long long)u << 32) | (unsigned)col;
}
__device__ __forceinline__ void cswap(unsigned long long& a, unsigned long long& b) {
    unsigned long long lo = min(a, b), hi = max(a, b);
    a = lo; b = hi;
}
// merge two sorted ascending quads, keep lowest 4 (sorted)
__device__ __forceinline__ void merge4(unsigned long long* k,
                                       unsigned long long o0, unsigned long long o1,
                                       unsigned long long o2, unsigned long long o3) {
    unsigned long long c0 = min(k[0], o3);
    unsigned long long c1 = min(k[1], o2);
    unsigned long long c2 = min(k[2], o1);
    unsigned long long c3 = min(k[3], o0);
    cswap(c0, c2); cswap(c1, c3); cswap(c0, c1); cswap(c2, c3);
    k[0] = c0; k[1] = c1; k[2] = c2; k[3] = c3;
}
// sorted insert into ascending quad
__device__ __forceinline__ void upd4(float dot, float rn, float wk, int col,
                                     unsigned long long* k) {
    float dist = __fsub_rn(__fadd_rn(rn, wk), __fmul_rn(2.f, dot));
    unsigned long long key = dist_key(dist, col);
    if (key < k[3]) {
        k[3] = key;
        cswap(k[2], k[3]); cswap(k[1], k[2]); cswap(k[0], k[1]);
    }
}

// -------- zero scalar accumulators --------
__global__ void zero_kernel() {
    if (threadIdx.x < 3) g_scal[threadIdx.x] = 0.0;
}

// -------- B split (bf16 hi) + wk2 + counts reset --------
__global__ void bsplit_kernel(const float* __restrict__ W) {
    int c = blockIdx.x, t = threadIdx.x;
    float w = W[(size_t)c*DIM + t];
    __nv_bfloat16 hb = __float2bfloat16(w);
    unsigned short hu = __bfloat16_as_ushort(hb);
    unsigned short hn = __shfl_down_sync(0xFFFFFFFFu, hu, 1);
    if ((t & 1) == 0) {
        g_Bbf[(size_t)c*128 + (t >> 1)] = (uint32_t)hu | ((uint32_t)hn << 16);
    }
    __shared__ float s[DIM];
    s[t] = __fmul_rn(w, w);
    __syncthreads();
    for (int off = 128; off > 0; off >>= 1) {
        if (t < off) s[t] = __fadd_rn(s[t], s[t+off]);
        __syncthreads();
    }
    if (t == 0) { g_wk2[c] = s[0]; g_counts[c] = 0; }
}

// -------- A split (bf16 hi) + rn2 --------
__global__ void asplit_kernel(const float* __restrict__ x, int first) {
    int n = blockIdx.x, t = threadIdx.x;
    const float* src = first ? x : g_resid;
    float v = src[(size_t)n*DIM + t];
    __nv_bfloat16 hb = __float2bfloat16(v);
    unsigned short hu = __bfloat16_as_ushort(hb);
    unsigned short hn = __shfl_down_sync(0xFFFFFFFFu, hu, 1);
    if ((t & 1) == 0) {
        g_Abf[(size_t)n*128 + (t >> 1)] = (uint32_t)hu | ((uint32_t)hn << 16);
    }
    __shared__ float s[DIM];
    s[t] = __fmul_rn(v, v);
    __syncthreads();
    for (int off = 128; off > 0; off >>= 1) {
        if (t < off) s[t] = __fadd_rn(s[t], s[t+off]);
        __syncthreads();
    }
    if (t == 0) g_rn2[n] = s[0];
}

// -------- pairwise distances (compact loss): tiled Gram kernel --------
#define PDK 32
__global__ void __launch_bounds__(256)
pdist_kernel(const float* __restrict__ W) {
    int b = blockIdx.x, ti = 0;
    while (b >= 8 - ti) { b -= 8 - ti; ti++; }
    int tj = ti + b;

    __shared__ float sA[PDK][128];
    __shared__ float sB[PDK][128];

    int t = threadIdx.x;
    int tx = t & 15, ty = t >> 4;
    int rowBase = ti * 128, colBase = tj * 128;

    float acc[8][8];
    #pragma unroll
    for (int i = 0; i < 8; i++)
        #pragma unroll
        for (int j = 0; j < 8; j++) acc[i][j] = 0.f;

    int lrow = t >> 1;
    int lc0  = (t & 1) * 16;

    for (int kc = 0; kc < DIM; kc += PDK) {
        #pragma unroll
        for (int q = 0; q < 4; q++) {
            float4 va = *(const float4*)&W[(size_t)(rowBase + lrow)*DIM + kc + lc0 + q*4];
            float4 vb = *(const float4*)&W[(size_t)(colBase + lrow)*DIM + kc + lc0 + q*4];
            sA[lc0 + q*4 + 0][lrow] = va.x; sA[lc0 + q*4 + 1][lrow] = va.y;
            sA[lc0 + q*4 + 2][lrow] = va.z; sA[lc0 + q*4 + 3][lrow] = va.w;
            sB[lc0 + q*4 + 0][lrow] = vb.x; sB[lc0 + q*4 + 1][lrow] = vb.y;
            sB[lc0 + q*4 + 2][lrow] = vb.z; sB[lc0 + q*4 + 3][lrow] = vb.w;
        }
        __syncthreads();
        #pragma unroll 8
        for (int k = 0; k < PDK; k++) {
            float4 a0 = *(const float4*)&sA[k][ty*8];
            float4 a1 = *(const float4*)&sA[k][ty*8 + 4];
            float4 b0 = *(const float4*)&sB[k][tx*8];
            float4 b1 = *(const float4*)&sB[k][tx*8 + 4];
            float a[8] = {a0.x,a0.y,a0.z,a0.w,a1.x,a1.y,a1.z,a1.w};
            float bb[8] = {b0.x,b0.y,b0.z,b0.w,b1.x,b1.y,b1.z,b1.w};
            #pragma unroll
            for (int i = 0; i < 8; i++)
                #pragma unroll
                for (int j = 0; j < 8; j++)
                    acc[i][j] = __fmaf_rn(a[i], bb[j], acc[i][j]);
        }
        __syncthreads();
    }

    double dsum = 0.0;
    #pragma unroll
    for (int i = 0; i < 8; i++) {
        int gi = rowBase + ty*8 + i;
        float sqi = g_wk2[gi];
        #pragma unroll
        for (int j = 0; j < 8; j++) {
            int gj = colBase + tx*8 + j;
            if (gj > gi) {
                float d2 = __fsub_rn(__fadd_rn(sqi, g_wk2[gj]),
                                     __fmul_rn(2.f, acc[i][j]));
                dsum += (double)sqrtf(fmaxf(d2, 0.f));
            }
        }
    }
    __shared__ double sd[256];
    sd[t] = dsum;
    __syncthreads();
    for (int off = 128; off > 0; off >>= 1) {
        if (t < off) sd[t] += sd[t+off];
        __syncthreads();
    }
    if (t == 0) g_pdpart[blockIdx.x] = sd[0];
}

// -------- chunk loader: A [128 x 16u32], B [128 x 16u32], padded stride 20 --------
__device__ __forceinline__ void load_chunk(int p, int rowBase, uint32_t smbase, int t) {
    int pass = p >> 3, c = p & 7, s = p & 1;
    uint32_t Ab = smbase + (uint32_t)(s * STAGE_BYTES);
    uint32_t Bb = Ab + A_BYTES;
    int koff = c * 16;
    int n0 = pass * GNP;
    #pragma unroll
    for (int i = 0; i < 2; i++) {
        int f = t + i*256;          // 0..511
        int row = f >> 2, seg = f & 3;
        cp16(Ab + (uint32_t)(row*(ROW_U32*4) + seg*16),
             g_Abf + (size_t)(rowBase + row)*128 + koff + seg*4);
        cp16(Bb + (uint32_t)(row*(ROW_U32*4) + seg*16),
             g_Bbf + (size_t)(n0 + row)*128 + koff + seg*4);
    }
    cp_commit();
}

// -------- main GEMM (1-term bf16 mma.sync m16n8k16) + top-4 argmin --------
__global__ void __launch_bounds__(256, 2)
gemm_argmin_kernel() {
    extern __shared__ float dynsm[];
    __shared__ unsigned long long sk[128][2][4];

    int t = threadIdx.x;
    int wid = t >> 5, lane = t & 31;
    int g = lane >> 2, tq = lane & 3;
    int warpRow = (wid >> 1) * 32;     // 4 row-groups of 32
    int warpCol = (wid & 1) * 64;      // 2 col-groups of 64
    int rowBase = blockIdx.x * GM;

    uint32_t smbase = smem_u32(dynsm);
    load_chunk(0, rowBase, smbase, t);
    load_chunk(1, rowBase, smbase, t);

    int r0 = rowBase + warpRow + g;
    float rn[4] = { g_rn2[r0], g_rn2[r0+8], g_rn2[r0+16], g_rn2[r0+24] };

    unsigned long long k4[4][4];
    #pragma unroll
    for (int i = 0; i < 4; i++)
        #pragma unroll
        for (int r = 0; r < 4; r++) k4[i][r] = KMAX;

    for (int pass = 0; pass < NPASS; pass++) {
        float acc[2][8][4];
        #pragma unroll
        for (int mi = 0; mi < 2; mi++)
            #pragma unroll
            for (int ni = 0; ni < 8; ni++)
                #pragma unroll
                for (int q = 0; q < 4; q++) acc[mi][ni][q] = 0.f;

        for (int c = 0; c < NCHUNK; c++) {
            int p = pass * NCHUNK + c, s = p & 1;
            if (p + 2 >= TOTCHUNK) cp_wait0(); else cp_wait1();
            __syncthreads();

            const uint32_t* As = (const uint32_t*)dynsm + (size_t)s * (STAGE_BYTES/4);
            const uint32_t* Bs = As + A_BYTES/4;

            #pragma unroll
            for (int ks = 0; ks < 2; ks++) {
                int k0 = ks * 8 + tq;
                uint32_t a[2][4];
                #pragma unroll
                for (int mi = 0; mi < 2; mi++) {
                    int rr = warpRow + mi*16 + g;
                    a[mi][0] = As[rr*ROW_U32 + k0];
                    a[mi][1] = As[(rr+8)*ROW_U32 + k0];
                    a[mi][2] = As[rr*ROW_U32 + k0 + 4];
                    a[mi][3] = As[(rr+8)*ROW_U32 + k0 + 4];
                }
                #pragma unroll
                for (int ni = 0; ni < 8; ni++) {
                    int cc = warpCol + ni*8 + g;
                    uint32_t b0 = Bs[cc*ROW_U32 + k0];
                    uint32_t b1 = Bs[cc*ROW_U32 + k0 + 4];
                    mma_bf16(acc[0][ni], a[0], b0, b1);
                    mma_bf16(acc[1][ni], a[1], b0, b1);
                }
            }
            __syncthreads();
            if (p + 2 < TOTCHUNK) load_chunk(p + 2, rowBase, smbase, t);
        }

        int n0 = pass * GNP;
        #pragma unroll
        for (int ni = 0; ni < 8; ni++) {
            int col = n0 + warpCol + ni*8 + 2*tq;
            float wka = __ldg(&g_wk2[col]);
            float wkb = __ldg(&g_wk2[col + 1]);
            #pragma unroll
            for (int mi = 0; mi < 2; mi++) {
                upd4(acc[mi][ni][0], rn[mi*2],   wka, col,   k4[mi*2]);
                upd4(acc[mi][ni][1], rn[mi*2],   wkb, col+1, k4[mi*2]);
                upd4(acc[mi][ni][2], rn[mi*2+1], wka, col,   k4[mi*2+1]);
                upd4(acc[mi][ni][3], rn[mi*2+1], wkb, col+1, k4[mi*2+1]);
            }
        }
    }

    // quad reduce: lanes sharing a row are l = g*4 + tq
    #pragma unroll
    for (int i = 0; i < 4; i++) {
        #pragma unroll
        for (int off = 1; off <= 2; off <<= 1) {
            unsigned long long o0 = __shfl_xor_sync(0xFFFFFFFFu, k4[i][0], off);
            unsigned long long o1 = __shfl_xor_sync(0xFFFFFFFFu, k4[i][1], off);
            unsigned long long o2 = __shfl_xor_sync(0xFFFFFFFFu, k4[i][2], off);
            unsigned long long o3 = __shfl_xor_sync(0xFFFFFFFFu, k4[i][3], off);
            merge4(k4[i], o0, o1, o2, o3);
        }
    }
    if (tq == 0) {
        #pragma unroll
        for (int i = 0; i < 4; i++)
            #pragma unroll
            for (int r = 0; r < 4; r++)
                sk[warpRow + g + i*8][wid & 1][r] = k4[i][r];
    }
    __syncthreads();
    if (t < 128) {
        unsigned long long m[4] = { sk[t][0][0], sk[t][0][1], sk[t][0][2], sk[t][0][3] };
        merge4(m, sk[t][1][0], sk[t][1][1], sk[t][1][2], sk[t][1][3]);
        g_top4[rowBase + t] = make_int4((int)(m[0] & 0xFFFFFFFFULL),
                                        (int)(m[1] & 0xFFFFFFFFULL),
                                        (int)(m[2] & 0xFFFFFFFFULL),
                                        (int)(m[3] & 0xFFFFFFFFULL));
    }
}

// -------- exact refine: sequential-FMA dots (R3-validated accumulation order) --------
__global__ void __launch_bounds__(64)
refine_kernel(const float* __restrict__ x, const float* __restrict__ W, int first) {
    int n = blockIdx.x, t = threadIdx.x;
    __shared__ float rs[DIM];
    __shared__ unsigned long long keys[4];
    int4 cand = g_top4[n];
    const float* src = first ? x : g_resid;
    float4 v = *(const float4*)&src[(size_t)n*DIM + t*4];
    rs[t*4+0] = v.x; rs[t*4+1] = v.y; rs[t*4+2] = v.z; rs[t*4+3] = v.w;
    __syncthreads();
    if (t < 4) {
        int c = (t == 0) ? cand.x : (t == 1) ? cand.y : (t == 2) ? cand.z : cand.w;
        const float* w = W + (size_t)c * DIM;
        float acc = 0.f;
        #pragma unroll 16
        for (int k = 0; k < DIM; k++)
            acc = __fmaf_rn(rs[k], __ldg(&w[k]), acc);
        float d = __fsub_rn(__fadd_rn(g_rn2[n], g_wk2[c]), __fmul_rn(2.f, acc));
        keys[t] = dist_key(d, c);
    }
    __syncthreads();
    if (t == 0) {
        unsigned long long bk = min(min(keys[0], keys[1]), min(keys[2], keys[3]));
        g_idx[n] = (int)(bk & 0xFFFFFFFFULL);
    }
}

// -------- per-row update: gather, straight-through, residual, losses --------
__global__ void update_kernel(const float* __restrict__ x, const float* __restrict__ W,
                              float* __restrict__ quant, float* __restrict__ out_idx,
                              int first) {
    int n = blockIdx.x, t = threadIdx.x;
    int idx = g_idx[n];
    size_t e = (size_t)n * DIM + t;
    const float* srcr = first ? x : g_resid;
    float r = srcr[e];
    float q = W[(size_t)idx * DIM + t];
    float diff = __fsub_rn(q, r);
    float qst  = __fadd_rn(r, diff);
    float qz   = first ? qst : __fadd_rn(quant[e], qst);
    quant[e] = qz;
    float rnew = __fsub_rn(x[e], qz);
    g_resid[e] = rnew;

    __shared__ double sd[DIM];
    sd[t] = (double)diff * (double)diff;
    __syncthreads();
    for (int off = 128; off > 0; off >>= 1) {
        if (t < off) sd[t] += sd[t+off];
        __syncthreads();
    }
    if (t == 0) {
        g_qpart[n] = sd[0];
        out_idx[n] = (float)idx;
        atomicAdd(&g_counts[idx], 1);
    }
}

// -------- per-level scalar reductions (deterministic) --------
__global__ void level_reduce_kernel() {
    __shared__ double sd[1024];
    int t = threadIdx.x;
    double a = 0.0;
    for (int i = t; i < NR; i += 1024) a += g_qpart[i];
    sd[t] = a;
    __syncthreads();
    for (int off = 512; off > 0; off >>= 1) {
        if (t < off) sd[t] += sd[t+off];
        __syncthreads();
    }
    if (t == 0) {
        double m = sd[0] / ((double)NR * (double)DIM);
        g_scal[0] += m + 0.25 * m;
    }
    __syncthreads();
    sd[t] = fabs((double)g_counts[t] - 64.0);
    __syncthreads();
    for (int off = 512; off > 0; off >>= 1) {
        if (t < off) sd[t] += sd[t+off];
        __syncthreads();
    }
    if (t == 0) g_scal[1] += sd[0] / (double)NCW;
    __syncthreads();
    sd[t] = (t < PD_BLOCKS) ? g_pdpart[t] : 0.0;
    __syncthreads();
    for (int off = 512; off > 0; off >>= 1) {
        if (t < off) sd[t] += sd[t+off];
        __syncthreads();
    }
    if (t == 0) g_scal[2] += 2.0 * (sd[0] / (double)NPAIRS);
}

__global__ void finalize_kernel(float* __restrict__ scal_out) {
    if (threadIdx.x < 3) scal_out[threadIdx.x] = (float)g_scal[threadIdx.x];
}

// -------- host driver --------
extern "C" void kernel_launch(void* const* d_in, const int* in_sizes, int n_in,
                              void* d_out, int out_size) {
    const float* x  = (const float*)d_in[0];
    const float* cb = (const float*)d_in[1];
    float* out   = (float*)d_out;
    float* quant = out;
    float* scal  = out + (size_t)NR * DIM;
    float* oidx  = scal + 3;

    cudaFuncSetAttribute(gemm_argmin_kernel,
                         cudaFuncAttributeMaxDynamicSharedMemorySize, DYN_SMEM);

    zero_kernel<<<1, 32>>>();
    for (int c = 0; c < NLEV; c++) {
        const float* W = cb + (size_t)c * NCW * DIM;
        int first = (c == 0) ? 1 : 0;
        bsplit_kernel<<<NCW, 256>>>(W);
        asplit_kernel<<<NR, 256>>>(x, first);
        pdist_kernel<<<PD_BLOCKS, 256>>>(W);
        gemm_argmin_kernel<<<NR/GM, 256, DYN_SMEM>>>();
        refine_kernel<<<NR, 64>>>(x, W, first);
        update_kernel<<<NR, 256>>>(x, W, quant, oidx + (size_t)c * NR, first);
        level_reduce_kernel<<<1, 1024>>>();
    }
    finalize_kernel<<<1, 32>>>(scal);
}